// round 14
// baseline (speedup 1.0000x reference)
#include <cuda_runtime.h>
#include <cuda_bf16.h>
#include <cstdint>

#define NB   8
#define NL   2048
#define NK   16
#define NATT 64
#define NEMB 32
#define NOUT 128
#define KCAP 96

typedef unsigned long long ull;

// ---------------- scratch (device globals; no allocations allowed) ----------
__device__ int            g_nidx[NB * NL * NK];
__device__ float4         g_cent[NB * NL];
__device__ __nv_bfloat16  g_outer_hi[(size_t)NB * NL * 2048];   // 64 MB
__device__ __nv_bfloat16  g_outer_lo[(size_t)NB * NL * 2048];   // 64 MB
__device__ __nv_bfloat16  g_esum_hi[NB * NL * NEMB];
__device__ __nv_bfloat16  g_esum_lo[NB * NL * NEMB];
__device__ __nv_bfloat16  g_bt_hi[2080 * 128];                  // [W12;K1] [k][n]
__device__ __nv_bfloat16  g_bt_lo[2080 * 128];

// ---------------- helpers ---------------------------------------------------
__device__ __forceinline__ void fma2(ull& d, ull a, ull b) {
    asm("fma.rn.f32x2 %0, %1, %2, %3;" : "=l"(d) : "l"(a), "l"(b), "l"(d));
}
__device__ __forceinline__ ull pack2(float x, float y) {
    ull r; asm("mov.b64 %0, {%1, %2};" : "=l"(r) : "f"(x), "f"(y)); return r;
}
__device__ __forceinline__ float2 unpack2(ull v) {
    float2 f; asm("mov.b64 {%0, %1}, %2;" : "=f"(f.x), "=f"(f.y) : "l"(v)); return f;
}
__device__ __forceinline__ uint32_t cvta_smem(const void* p) {
    uint32_t a;
    asm("{ .reg .u64 t; cvta.to.shared.u64 t, %1; cvt.u32.u64 %0, t; }"
        : "=r"(a) : "l"(p));
    return a;
}
__device__ __forceinline__ void cpasync16(uint32_t dst, const void* src) {
    asm volatile("cp.async.cg.shared.global [%0], [%1], 16;"
                 :: "r"(dst), "l"(src) : "memory");
}
__device__ __forceinline__ ull umin64(ull a, ull b) { return a < b ? a : b; }

// ============================================================================
// Kernel A0: pack centers
// ============================================================================
__global__ __launch_bounds__(256) void pack_centers(const float* __restrict__ frame)
{
    int i = blockIdx.x * 256 + threadIdx.x;
    const float* p = frame + (size_t)i * 12;
    float x = p[0], y = p[1], z = p[2];
    float sq = fmaf(x, x, fmaf(y, y, z * z));
    g_cent[i] = make_float4(x, y, z, sq);
}

// ============================================================================
// Kernel W: split [W12;K1] -> bf16 hi/lo, layout [k][n] (k = 0..2079)
// ============================================================================
__global__ __launch_bounds__(256) void wsplit_kernel(
    const float* __restrict__ W12, const float* __restrict__ K1)
{
    int idx = blockIdx.x * 256 + threadIdx.x;
    float v;
    if (idx < 2048 * 128) v = W12[idx];
    else                  v = K1[idx - 2048 * 128];
    __nv_bfloat16 hi = __float2bfloat16_rn(v);
    __nv_bfloat16 lo = __float2bfloat16_rn(v - __bfloat162float(hi));
    g_bt_hi[idx] = hi;
    g_bt_lo[idx] = lo;
}

// ============================================================================
// Kernel A: KNN threshold-collect (unchanged from R13)
// ============================================================================
__global__ __launch_bounds__(256) void knn_kernel()
{
    __shared__ ull s_buf[8][KCAP];
    __shared__ ull s_merge[8][32 * 16];     // fallback only

    const int w    = threadIdx.x >> 5;
    const int lane = threadIdx.x & 31;
    const int q    = blockIdx.x * 8 + w;
    const int b    = q >> 11;

    const float4* __restrict__ cent = g_cent + b * NL;
    const float4 cq = cent[q & 2047];
    int* o = g_nidx + (size_t)q * NK;

    float m1 = __int_as_float(0x7F800000);
#pragma unroll 4
    for (int r = 0; r < 64; r++) {
        const int m = r * 32 + lane;
        float4 c = cent[m];
        float dot = fmaf(cq.x, c.x, fmaf(cq.y, c.y, cq.z * c.z));
        float d2  = fmaf(-2.0f, dot, cq.w + c.w);
        d2 = fmaxf(d2, 0.0f);
        m1 = fminf(m1, d2);
    }

    float v = m1;
#pragma unroll
    for (int k = 2; k <= 32; k <<= 1) {
#pragma unroll
        for (int j = k >> 1; j > 0; j >>= 1) {
            float ov = __shfl_xor_sync(0xFFFFFFFFu, v, j);
            bool up    = (lane & k) == 0;
            bool small = (lane & j) == 0;
            v = (small == up) ? fminf(v, ov) : fmaxf(v, ov);
        }
    }
    const float t = __shfl_sync(0xFFFFFFFFu, v, 15);

    int base = 0;
#pragma unroll 4
    for (int r = 0; r < 64; r++) {
        const int m = r * 32 + lane;
        float4 c = cent[m];
        float dot = fmaf(cq.x, c.x, fmaf(cq.y, c.y, cq.z * c.z));
        float d2  = fmaf(-2.0f, dot, cq.w + c.w);
        d2 = fmaxf(d2, 0.0f);
        bool keep = (d2 <= t);
        unsigned bal = __ballot_sync(0xFFFFFFFFu, keep);
        if (keep) {
            int pos = base + __popc(bal & ((1u << lane) - 1u));
            if (pos < KCAP)
                s_buf[w][pos] = ((ull)__float_as_uint(d2) << 32) | (unsigned)m;
        }
        base += __popc(bal);
    }
    __syncwarp();

    if (base <= KCAP) {
        for (int i = lane; i < KCAP; i += 32)
            if (i >= base) s_buf[w][i] = 0xFFFFFFFFFFFFFFFFull;
        __syncwarp();

        ull a0 = s_buf[w][lane];
        ull a1 = s_buf[w][lane + 32];
        ull a2 = s_buf[w][lane + 64];
#pragma unroll
        for (int r = 0; r < 16; r++) {
            ull mv = umin64(a0, umin64(a1, a2));
#pragma unroll
            for (int off = 16; off > 0; off >>= 1) {
                ull ov = __shfl_xor_sync(0xFFFFFFFFu, mv, off);
                mv = umin64(mv, ov);
            }
            if (a0 == mv)      a0 = 0xFFFFFFFFFFFFFFFFull;
            else if (a1 == mv) a1 = 0xFFFFFFFFFFFFFFFFull;
            else if (a2 == mv) a2 = 0xFFFFFFFFFFFFFFFFull;
            if (lane == 0) o[r] = (int)(unsigned)(mv & 0xFFFFFFFFull);
        }
    } else {
        float dl[16];
        int   il[16];
#pragma unroll
        for (int s = 0; s < 16; s++) { dl[s] = __int_as_float(0x7F800000); il[s] = -1; }
        for (int r = 0; r < 64; r++) {
            const int m = r * 32 + lane;
            float4 c = cent[m];
            float dot = fmaf(cq.x, c.x, fmaf(cq.y, c.y, cq.z * c.z));
            float d2  = fmaf(-2.0f, dot, cq.w + c.w);
            d2 = fmaxf(d2, 0.0f);
            if (d2 < dl[15]) {
                float cd = d2; int ci = m;
#pragma unroll
                for (int s = 0; s < 16; s++) {
                    bool  lt = cd < dl[s];
                    float td = dl[s]; int ti = il[s];
                    dl[s] = lt ? cd : td;  il[s] = lt ? ci : ti;
                    cd    = lt ? td : cd;  ci    = lt ? ti : ci;
                }
            }
        }
        ull* my = &s_merge[w][lane * 16];
#pragma unroll
        for (int s = 0; s < 16; s++)
            my[s] = ((ull)__float_as_uint(dl[s]) << 32) | (unsigned)il[s];
        __syncwarp();
        int p = 0;
        ull h = my[0];
        for (int r = 0; r < 16; r++) {
            ull mv = h;
#pragma unroll
            for (int off = 16; off > 0; off >>= 1) {
                ull ov = __shfl_xor_sync(0xFFFFFFFFu, mv, off);
                mv = umin64(mv, ov);
            }
            if (h == mv) {
                p++;
                h = (p < 16) ? my[p] : 0xFFFFFFFFFFFFFFFFull;
            }
            if (lane == 0) o[r] = (int)(unsigned)(mv & 0xFFFFFFFFull);
        }
    }
}

// ============================================================================
// Kernel B: feat — R13 structure, gaussian reads smem (low live regs),
// __launch_bounds__(128, 8): cap ~64 regs -> 8 blocks/SM (occ ~50%).
// ============================================================================
__global__ __launch_bounds__(128, 8) void feat_kernel(
    const float* __restrict__ attr,
    const float* __restrict__ frame,
    const int*   __restrict__ aidx,
    const float* __restrict__ gkc,
    const float* __restrict__ gkp)
{
    __shared__ int   s_nidx[NK];
    __shared__ float s_coords[NK][8];
    __shared__ float s_cent[32][9];
    __shared__ float s_prec[32][49];
    __shared__ float s_attr[NK][64];
    __shared__ float s_emb[NK][32];

    const int bl  = blockIdx.x;
    const int b   = bl >> 11;
    const int tid = threadIdx.x;

    if (tid < NK) s_nidx[tid] = g_nidx[(size_t)bl * NK + tid];
    for (int i = tid; i < 7 * 32; i += 128)
        s_cent[i & 31][i >> 5] = gkc[i];
    for (int i = tid; i < 49 * 32; i += 128)
        s_prec[i & 31][i >> 5] = gkp[i];
    __syncthreads();

    for (int i = tid; i < NK * 16; i += 128) {
        int k = i >> 4, j4 = i & 15;
        const float4* src = (const float4*)&attr[((size_t)(b * NL + s_nidx[k])) * 64];
        ((float4*)&s_attr[k][0])[j4] = src[j4];
    }

    if (tid < NK) {
        const int k = tid;
        const int m = s_nidx[k];
        const size_t gs = (size_t)bl * 12;
        const size_t gn = (size_t)(b * NL + m) * 12;

        float cx = frame[gs + 0], cy = frame[gs + 1], cz = frame[gs + 2];
        float r0x = frame[gs + 3], r0y = frame[gs + 4],  r0z = frame[gs + 5];
        float r1x = frame[gs + 6], r1y = frame[gs + 7],  r1z = frame[gs + 8];
        float r2x = frame[gs + 9], r2y = frame[gs + 10], r2z = frame[gs + 11];

        float dx = frame[gn + 0] - cx, dy = frame[gn + 1] - cy, dz = frame[gn + 2] - cz;
        float znx = frame[gn + 9], zny = frame[gn + 10], znz = frame[gn + 11];

        float e0 = dx * r0x + dy * r0y + dz * r0z;
        float e1 = dx * r1x + dy * r1y + dz * r1z;
        float e2 = dx * r2x + dy * r2y + dz * r2z;

        float idxs = (float)aidx[bl];
        float idxn = (float)aidx[b * NL + m];
        float idist = fminf(fabsf(idxn - idxs), 8.0f);

        float zz   = znx * r2x + zny * r2y + znz * r2z;
        float dist = sqrtf(dx * dx + dy * dy + dz * dz + 1e-6f);
        float ddz  = e2 / dist;
        float zdd  = (znx * dx + zny * dy + znz * dz) / dist;

        s_coords[k][0] = e0;  s_coords[k][1] = e1;  s_coords[k][2] = e2;
        s_coords[k][3] = idist; s_coords[k][4] = zz;
        s_coords[k][5] = ddz;   s_coords[k][6] = zdd; s_coords[k][7] = 0.0f;
    }
    __syncthreads();

    // gaussian: smem reads (conflict-free strides), low live registers
#pragma unroll
    for (int it = tid; it < NK * 32; it += 128) {
        int k = it >> 5, n = it & 31;
        float y0 = 0, y1 = 0, y2 = 0, y3 = 0, y4 = 0, y5 = 0, y6 = 0;
#pragma unroll
        for (int d = 0; d < 7; d++) {
            float diff = s_coords[k][d] - s_cent[n][d];
            const float* pp = &s_prec[n][d * 7];
            y0 = fmaf(diff, pp[0], y0);
            y1 = fmaf(diff, pp[1], y1);
            y2 = fmaf(diff, pp[2], y2);
            y3 = fmaf(diff, pp[3], y3);
            y4 = fmaf(diff, pp[4], y4);
            y5 = fmaf(diff, pp[5], y5);
            y6 = fmaf(diff, pp[6], y6);
        }
        float s = y0 * y0 + y1 * y1 + y2 * y2 + y3 * y3 + y4 * y4 + y5 * y5 + y6 * y6;
        s_emb[k][n] = __expf(-0.5f * s);
    }
    __syncthreads();

    if (tid < 32) {
        float s = 0.0f;
#pragma unroll
        for (int k = 0; k < NK; k++) s += s_emb[k][tid];
        __nv_bfloat16 h = __float2bfloat16_rn(s);
        g_esum_hi[(size_t)bl * 32 + tid] = h;
        g_esum_lo[(size_t)bl * 32 + tid] = __float2bfloat16_rn(s - __bfloat162float(h));
    }

    // ---- outer: R10-exact (j = tid&63 column, iq row-quarter) ----
    const int j  = tid & 63;
    const int iq = tid >> 6;
    ull acc2[8];
#pragma unroll
    for (int r = 0; r < 8; r++) acc2[r] = 0ull;
#pragma unroll
    for (int k = 0; k < NK; k++) {
        float a = s_attr[k][j];
        ull ap = pack2(a, a);
        const ulonglong2* ep = (const ulonglong2*)&s_emb[k][iq * 16];
        ulonglong2 e0 = ep[0], e1 = ep[1];
        fma2(acc2[0], e0.x, ap); fma2(acc2[1], e0.y, ap);
        fma2(acc2[2], e1.x, ap); fma2(acc2[3], e1.y, ap);
        ulonglong2 e2 = ep[2], e3 = ep[3];
        fma2(acc2[4], e2.x, ap); fma2(acc2[5], e2.y, ap);
        fma2(acc2[6], e3.x, ap); fma2(acc2[7], e3.y, ap);
    }
    size_t base = (size_t)bl * 2048 + (size_t)iq * 1024 + j;
#pragma unroll
    for (int r = 0; r < 8; r++) {
        float2 f = unpack2(acc2[r]);
        size_t i0 = base + (size_t)(2 * r) * 64;
        size_t i1 = base + (size_t)(2 * r + 1) * 64;
        __nv_bfloat16 h0 = __float2bfloat16_rn(f.x);
        __nv_bfloat16 h1 = __float2bfloat16_rn(f.y);
        g_outer_hi[i0] = h0;
        g_outer_hi[i1] = h1;
        g_outer_lo[i0] = __float2bfloat16_rn(f.x - __bfloat162float(h0));
        g_outer_lo[i1] = __float2bfloat16_rn(f.y - __bfloat162float(h1));
    }
}

// ============================================================================
// Kernel C: HMMA GEMM, M=128 per CTA (unchanged from R13)
// ============================================================================
#define LDA 72
#define LDB 136
#define ASZ (128 * LDA * 2)             // 18432 B per A buffer
#define BSZ (64 * LDB * 2)              // 17408 B per B buffer
#define BUFSZ (2 * ASZ + 2 * BSZ)       // 71680 B  [Ah][Al][Bh][Bl]
#define GEMM_SMEM (2 * BUFSZ)           // 143360 B

__device__ __forceinline__ void ldm_x4(uint32_t& r0, uint32_t& r1,
                                       uint32_t& r2, uint32_t& r3, uint32_t a) {
    asm volatile("ldmatrix.sync.aligned.m8n8.x4.shared.b16 {%0,%1,%2,%3}, [%4];"
                 : "=r"(r0), "=r"(r1), "=r"(r2), "=r"(r3) : "r"(a));
}
__device__ __forceinline__ void ldm_x4t(uint32_t& r0, uint32_t& r1,
                                        uint32_t& r2, uint32_t& r3, uint32_t a) {
    asm volatile("ldmatrix.sync.aligned.m8n8.x4.trans.shared.b16 {%0,%1,%2,%3}, [%4];"
                 : "=r"(r0), "=r"(r1), "=r"(r2), "=r"(r3) : "r"(a));
}
__device__ __forceinline__ void mma_bf16(float* d, const uint32_t* a,
                                         uint32_t b0, uint32_t b1) {
    asm volatile(
        "mma.sync.aligned.m16n8k16.row.col.f32.bf16.bf16.f32 "
        "{%0,%1,%2,%3}, {%4,%5,%6,%7}, {%8,%9}, {%0,%1,%2,%3};"
        : "+f"(d[0]), "+f"(d[1]), "+f"(d[2]), "+f"(d[3])
        : "r"(a[0]), "r"(a[1]), "r"(a[2]), "r"(a[3]), "r"(b0), "r"(b1));
}

extern __shared__ uint8_t g_dsm[];

__global__ __launch_bounds__(256) void gemm_mma(
    const float* __restrict__ bias, float* __restrict__ out)
{
    const int tid    = threadIdx.x;
    const int wid    = tid >> 5;
    const int lane   = tid & 31;
    const int warp_m = wid & 3;          // 4 m-groups of 32 rows
    const int warp_n = wid >> 2;         // 2 n-groups of 64 cols
    const int rowBase = blockIdx.x * 128;

    const uint32_t smem0 = cvta_smem(g_dsm);

    const int r_a = tid >> 1;            // 0..127 (A row)
    const int h_a = (tid & 1) * 32;      // A col half (bf16)
    const int k_b = tid >> 2;            // 0..63  (B k-row)
    const int q_b = (tid & 3) * 32;      // B col quarter

    const int lrow = (lane & 7) + ((lane >> 3) & 1) * 8;
    const int lcol = (lane >> 4) * 8;
    const uint32_t aOffBase = (uint32_t)((warp_m * 32 + lrow) * LDA + lcol) * 2;
    const uint32_t bOffBase = (uint32_t)(lrow * LDB + warp_n * 64 + lcol) * 2;

    float acc[2][8][4];
#pragma unroll
    for (int mt = 0; mt < 2; mt++)
#pragma unroll
        for (int nt = 0; nt < 8; nt++)
#pragma unroll
            for (int r = 0; r < 4; r++) acc[mt][nt][r] = 0.0f;

    auto load_chunk = [&](int c, uint32_t sb) {
        const uint32_t sAh = sb, sAl = sb + ASZ, sBh = sb + 2 * ASZ, sBl = sb + 2 * ASZ + BSZ;
        if (c < 32) {
            const size_t aix = (size_t)(rowBase + r_a) * 2048 + c * 64 + h_a;
            const uint32_t aoff = (uint32_t)(r_a * LDA + h_a) * 2;
#pragma unroll
            for (int g = 0; g < 4; g++) {
                cpasync16(sAh + aoff + g * 16, &g_outer_hi[aix + g * 8]);
                cpasync16(sAl + aoff + g * 16, &g_outer_lo[aix + g * 8]);
            }
            const size_t bix = (size_t)(c * 64 + k_b) * 128 + q_b;
            const uint32_t boff = (uint32_t)(k_b * LDB + q_b) * 2;
#pragma unroll
            for (int g = 0; g < 4; g++) {
                cpasync16(sBh + boff + g * 16, &g_bt_hi[bix + g * 8]);
                cpasync16(sBl + boff + g * 16, &g_bt_lo[bix + g * 8]);
            }
        } else {
#pragma unroll
            for (int s = 0; s < 2; s++) {
                int idx = tid + s * 256;          // 0..511
                int row = idx >> 2;
                int ch  = idx & 3;                // 8-col chunk
                const size_t aix = (size_t)(rowBase + row) * 32 + ch * 8;
                const uint32_t aoff = (uint32_t)(row * LDA + ch * 8) * 2;
                cpasync16(sAh + aoff, &g_esum_hi[aix]);
                cpasync16(sAl + aoff, &g_esum_lo[aix]);
            }
#pragma unroll
            for (int s = 0; s < 2; s++) {
                int idx = tid + s * 256;          // 0..511
                int k   = idx >> 4;
                int ch  = idx & 15;               // 8-col chunk
                const size_t bix = (size_t)(2048 + k) * 128 + ch * 8;
                const uint32_t boff = (uint32_t)(k * LDB + ch * 8) * 2;
                cpasync16(sBh + boff, &g_bt_hi[bix]);
                cpasync16(sBl + boff, &g_bt_lo[bix]);
            }
        }
        asm volatile("cp.async.commit_group;" ::: "memory");
    };

    load_chunk(0, smem0);

    for (int c = 0; c <= 32; c++) {
        if (c < 32) load_chunk(c + 1, smem0 + ((c + 1) & 1) * BUFSZ);

        if (c < 32) asm volatile("cp.async.wait_group 1;" ::: "memory");
        else        asm volatile("cp.async.wait_group 0;" ::: "memory");
        __syncthreads();

        const uint32_t sb = smem0 + (c & 1) * BUFSZ;
        const uint32_t sAh = sb, sAl = sb + ASZ, sBh = sb + 2 * ASZ, sBl = sb + 2 * ASZ + BSZ;

        const int nks = (c == 32) ? 2 : 4;
        for (int ks = 0; ks < nks; ks++) {
            const uint32_t aAdd = (uint32_t)(ks * 16) * 2;
            const uint32_t bAdd = (uint32_t)(ks * 16 * LDB) * 2;
            uint32_t ah[2][4], al[2][4];
#pragma unroll
            for (int mt = 0; mt < 2; mt++) {
                uint32_t ao = aOffBase + (uint32_t)(mt * 16 * LDA) * 2 + aAdd;
                ldm_x4(ah[mt][0], ah[mt][1], ah[mt][2], ah[mt][3], sAh + ao);
                ldm_x4(al[mt][0], al[mt][1], al[mt][2], al[mt][3], sAl + ao);
            }
#pragma unroll
            for (int ng = 0; ng < 4; ng++) {
                uint32_t bo = bOffBase + (uint32_t)(ng * 16) * 2 + bAdd;
                uint32_t bh0, bh1, bh2, bh3, bl0, bl1, bl2, bl3;
                ldm_x4t(bh0, bh1, bh2, bh3, sBh + bo);
                ldm_x4t(bl0, bl1, bl2, bl3, sBl + bo);
#pragma unroll
                for (int mt = 0; mt < 2; mt++) {
                    mma_bf16(acc[mt][ng * 2],     ah[mt], bh0, bh1);
                    mma_bf16(acc[mt][ng * 2],     ah[mt], bl0, bl1);
                    mma_bf16(acc[mt][ng * 2],     al[mt], bh0, bh1);
                    mma_bf16(acc[mt][ng * 2 + 1], ah[mt], bh2, bh3);
                    mma_bf16(acc[mt][ng * 2 + 1], ah[mt], bl2, bl3);
                    mma_bf16(acc[mt][ng * 2 + 1], al[mt], bh2, bh3);
                }
            }
        }
        __syncthreads();
    }

    const int gId = lane >> 2;
    const int tig = lane & 3;
#pragma unroll
    for (int mt = 0; mt < 2; mt++) {
#pragma unroll
        for (int nt = 0; nt < 8; nt++) {
            int col = warp_n * 64 + nt * 8 + tig * 2;
            float2 bv = *(const float2*)&bias[col];
            int m0 = rowBase + warp_m * 32 + mt * 16 + gId;
            float2 v0 = make_float2(acc[mt][nt][0] + bv.x, acc[mt][nt][1] + bv.y);
            float2 v1 = make_float2(acc[mt][nt][2] + bv.x, acc[mt][nt][3] + bv.y);
            *(float2*)&out[(size_t)m0 * 128 + col]       = v0;
            *(float2*)&out[(size_t)(m0 + 8) * 128 + col] = v1;
        }
    }
}

// ============================================================================
extern "C" void kernel_launch(void* const* d_in, const int* in_sizes, int n_in,
                              void* d_out, int out_size)
{
    const float* attr  = (const float*)d_in[0];
    const float* frame = (const float*)d_in[1];
    const int*   aidx  = (const int*)  d_in[2];
    // d_in[3] = labels (unused)
    const float* gkc   = (const float*)d_in[4];
    const float* gkp   = (const float*)d_in[5];
    const float* W12   = (const float*)d_in[6];
    const float* K1    = (const float*)d_in[7];
    const float* bias  = (const float*)d_in[8];
    float* out = (float*)d_out;

    static bool attr_set = false;
    if (!attr_set) {
        cudaFuncSetAttribute(gemm_mma, cudaFuncAttributeMaxDynamicSharedMemorySize,
                             GEMM_SMEM);
        attr_set = true;
    }

    pack_centers<<<64, 256>>>(frame);
    knn_kernel<<<2048, 256>>>();
    wsplit_kernel<<<1040, 256>>>(W12, K1);
    feat_kernel<<<NB * NL, 128>>>(attr, frame, aidx, gkc, gkp);
    gemm_mma<<<128, 256, GEMM_SMEM>>>(bias, out);
}

// round 15
// speedup vs baseline: 1.0962x; 1.0962x over previous
#include <cuda_runtime.h>
#include <cuda_bf16.h>
#include <cstdint>

#define NB   8
#define NL   2048
#define NK   16
#define NATT 64
#define NEMB 32
#define NOUT 128
#define KCAP 96

typedef unsigned long long ull;

// ---------------- scratch (device globals; no allocations allowed) ----------
__device__ int            g_nidx[NB * NL * NK];
__device__ float4         g_cent[NB * NL];
__device__ __nv_bfloat16  g_outer_hi[(size_t)NB * NL * 2048];   // 64 MB
__device__ __nv_bfloat16  g_outer_lo[(size_t)NB * NL * 2048];   // 64 MB
__device__ __nv_bfloat16  g_esum_hi[NB * NL * NEMB];
__device__ __nv_bfloat16  g_esum_lo[NB * NL * NEMB];
__device__ __nv_bfloat16  g_bt_hi[2080 * 128];                  // [W12;K1] [k][n]
__device__ __nv_bfloat16  g_bt_lo[2080 * 128];

// ---------------- helpers ---------------------------------------------------
__device__ __forceinline__ void fma2(ull& d, ull a, ull b) {
    asm("fma.rn.f32x2 %0, %1, %2, %3;" : "=l"(d) : "l"(a), "l"(b), "l"(d));
}
__device__ __forceinline__ ull pack2(float x, float y) {
    ull r; asm("mov.b64 %0, {%1, %2};" : "=l"(r) : "f"(x), "f"(y)); return r;
}
__device__ __forceinline__ float2 unpack2(ull v) {
    float2 f; asm("mov.b64 {%0, %1}, %2;" : "=f"(f.x), "=f"(f.y) : "l"(v)); return f;
}
__device__ __forceinline__ uint32_t cvta_smem(const void* p) {
    uint32_t a;
    asm("{ .reg .u64 t; cvta.to.shared.u64 t, %1; cvt.u32.u64 %0, t; }"
        : "=r"(a) : "l"(p));
    return a;
}
__device__ __forceinline__ void cpasync16(uint32_t dst, const void* src) {
    asm volatile("cp.async.cg.shared.global [%0], [%1], 16;"
                 :: "r"(dst), "l"(src) : "memory");
}
__device__ __forceinline__ ull umin64(ull a, ull b) { return a < b ? a : b; }

// ============================================================================
// Kernel A0: pack centers
// ============================================================================
__global__ __launch_bounds__(256) void pack_centers(const float* __restrict__ frame)
{
    int i = blockIdx.x * 256 + threadIdx.x;
    const float* p = frame + (size_t)i * 12;
    float x = p[0], y = p[1], z = p[2];
    float sq = fmaf(x, x, fmaf(y, y, z * z));
    g_cent[i] = make_float4(x, y, z, sq);
}

// ============================================================================
// Kernel W: split [W12;K1] -> bf16 hi/lo, layout [k][n] (k = 0..2079)
// ============================================================================
__global__ __launch_bounds__(256) void wsplit_kernel(
    const float* __restrict__ W12, const float* __restrict__ K1)
{
    int idx = blockIdx.x * 256 + threadIdx.x;
    float v;
    if (idx < 2048 * 128) v = W12[idx];
    else                  v = K1[idx - 2048 * 128];
    __nv_bfloat16 hi = __float2bfloat16_rn(v);
    __nv_bfloat16 lo = __float2bfloat16_rn(v - __bfloat162float(hi));
    g_bt_hi[idx] = hi;
    g_bt_lo[idx] = lo;
}

// ============================================================================
// Kernel A: KNN threshold-collect (unchanged from R13)
// ============================================================================
__global__ __launch_bounds__(256) void knn_kernel()
{
    __shared__ ull s_buf[8][KCAP];
    __shared__ ull s_merge[8][32 * 16];     // fallback only

    const int w    = threadIdx.x >> 5;
    const int lane = threadIdx.x & 31;
    const int q    = blockIdx.x * 8 + w;
    const int b    = q >> 11;

    const float4* __restrict__ cent = g_cent + b * NL;
    const float4 cq = cent[q & 2047];
    int* o = g_nidx + (size_t)q * NK;

    float m1 = __int_as_float(0x7F800000);
#pragma unroll 4
    for (int r = 0; r < 64; r++) {
        const int m = r * 32 + lane;
        float4 c = cent[m];
        float dot = fmaf(cq.x, c.x, fmaf(cq.y, c.y, cq.z * c.z));
        float d2  = fmaf(-2.0f, dot, cq.w + c.w);
        d2 = fmaxf(d2, 0.0f);
        m1 = fminf(m1, d2);
    }

    float v = m1;
#pragma unroll
    for (int k = 2; k <= 32; k <<= 1) {
#pragma unroll
        for (int j = k >> 1; j > 0; j >>= 1) {
            float ov = __shfl_xor_sync(0xFFFFFFFFu, v, j);
            bool up    = (lane & k) == 0;
            bool small = (lane & j) == 0;
            v = (small == up) ? fminf(v, ov) : fmaxf(v, ov);
        }
    }
    const float t = __shfl_sync(0xFFFFFFFFu, v, 15);

    int base = 0;
#pragma unroll 4
    for (int r = 0; r < 64; r++) {
        const int m = r * 32 + lane;
        float4 c = cent[m];
        float dot = fmaf(cq.x, c.x, fmaf(cq.y, c.y, cq.z * c.z));
        float d2  = fmaf(-2.0f, dot, cq.w + c.w);
        d2 = fmaxf(d2, 0.0f);
        bool keep = (d2 <= t);
        unsigned bal = __ballot_sync(0xFFFFFFFFu, keep);
        if (keep) {
            int pos = base + __popc(bal & ((1u << lane) - 1u));
            if (pos < KCAP)
                s_buf[w][pos] = ((ull)__float_as_uint(d2) << 32) | (unsigned)m;
        }
        base += __popc(bal);
    }
    __syncwarp();

    if (base <= KCAP) {
        for (int i = lane; i < KCAP; i += 32)
            if (i >= base) s_buf[w][i] = 0xFFFFFFFFFFFFFFFFull;
        __syncwarp();

        ull a0 = s_buf[w][lane];
        ull a1 = s_buf[w][lane + 32];
        ull a2 = s_buf[w][lane + 64];
#pragma unroll
        for (int r = 0; r < 16; r++) {
            ull mv = umin64(a0, umin64(a1, a2));
#pragma unroll
            for (int off = 16; off > 0; off >>= 1) {
                ull ov = __shfl_xor_sync(0xFFFFFFFFu, mv, off);
                mv = umin64(mv, ov);
            }
            if (a0 == mv)      a0 = 0xFFFFFFFFFFFFFFFFull;
            else if (a1 == mv) a1 = 0xFFFFFFFFFFFFFFFFull;
            else if (a2 == mv) a2 = 0xFFFFFFFFFFFFFFFFull;
            if (lane == 0) o[r] = (int)(unsigned)(mv & 0xFFFFFFFFull);
        }
    } else {
        float dl[16];
        int   il[16];
#pragma unroll
        for (int s = 0; s < 16; s++) { dl[s] = __int_as_float(0x7F800000); il[s] = -1; }
        for (int r = 0; r < 64; r++) {
            const int m = r * 32 + lane;
            float4 c = cent[m];
            float dot = fmaf(cq.x, c.x, fmaf(cq.y, c.y, cq.z * c.z));
            float d2  = fmaf(-2.0f, dot, cq.w + c.w);
            d2 = fmaxf(d2, 0.0f);
            if (d2 < dl[15]) {
                float cd = d2; int ci = m;
#pragma unroll
                for (int s = 0; s < 16; s++) {
                    bool  lt = cd < dl[s];
                    float td = dl[s]; int ti = il[s];
                    dl[s] = lt ? cd : td;  il[s] = lt ? ci : ti;
                    cd    = lt ? td : cd;  ci    = lt ? ti : ci;
                }
            }
        }
        ull* my = &s_merge[w][lane * 16];
#pragma unroll
        for (int s = 0; s < 16; s++)
            my[s] = ((ull)__float_as_uint(dl[s]) << 32) | (unsigned)il[s];
        __syncwarp();
        int p = 0;
        ull h = my[0];
        for (int r = 0; r < 16; r++) {
            ull mv = h;
#pragma unroll
            for (int off = 16; off > 0; off >>= 1) {
                ull ov = __shfl_xor_sync(0xFFFFFFFFu, mv, off);
                mv = umin64(mv, ov);
            }
            if (h == mv) {
                p++;
                h = (p < 16) ? my[p] : 0xFFFFFFFFFFFFFFFFull;
            }
            if (lane == 0) o[r] = (int)(unsigned)(mv & 0xFFFFFFFFull);
        }
    }
}

// ============================================================================
// Kernel B: feat — R13-exact (measured 115.68 us; regs=80, occ 35%)
// ============================================================================
__global__ __launch_bounds__(128) void feat_kernel(
    const float* __restrict__ attr,
    const float* __restrict__ frame,
    const int*   __restrict__ aidx,
    const float* __restrict__ gkc,
    const float* __restrict__ gkp)
{
    __shared__ int   s_nidx[NK];
    __shared__ float s_coords[NK][8];
    __shared__ float s_cent[32][9];
    __shared__ float s_prec[32][49];
    __shared__ float s_attr[NK][64];
    __shared__ float s_emb[NK][32];

    const int bl  = blockIdx.x;
    const int b   = bl >> 11;
    const int tid = threadIdx.x;

    if (tid < NK) s_nidx[tid] = g_nidx[(size_t)bl * NK + tid];
    for (int i = tid; i < 7 * 32; i += 128)
        s_cent[i & 31][i >> 5] = gkc[i];
    for (int i = tid; i < 49 * 32; i += 128)
        s_prec[i & 31][i >> 5] = gkp[i];
    __syncthreads();

    for (int i = tid; i < NK * 16; i += 128) {
        int k = i >> 4, j4 = i & 15;
        const float4* src = (const float4*)&attr[((size_t)(b * NL + s_nidx[k])) * 64];
        ((float4*)&s_attr[k][0])[j4] = src[j4];
    }

    if (tid < NK) {
        const int k = tid;
        const int m = s_nidx[k];
        const size_t gs = (size_t)bl * 12;
        const size_t gn = (size_t)(b * NL + m) * 12;

        float cx = frame[gs + 0], cy = frame[gs + 1], cz = frame[gs + 2];
        float r0x = frame[gs + 3], r0y = frame[gs + 4],  r0z = frame[gs + 5];
        float r1x = frame[gs + 6], r1y = frame[gs + 7],  r1z = frame[gs + 8];
        float r2x = frame[gs + 9], r2y = frame[gs + 10], r2z = frame[gs + 11];

        float dx = frame[gn + 0] - cx, dy = frame[gn + 1] - cy, dz = frame[gn + 2] - cz;
        float znx = frame[gn + 9], zny = frame[gn + 10], znz = frame[gn + 11];

        float e0 = dx * r0x + dy * r0y + dz * r0z;
        float e1 = dx * r1x + dy * r1y + dz * r1z;
        float e2 = dx * r2x + dy * r2y + dz * r2z;

        float idxs = (float)aidx[bl];
        float idxn = (float)aidx[b * NL + m];
        float idist = fminf(fabsf(idxn - idxs), 8.0f);

        float zz   = znx * r2x + zny * r2y + znz * r2z;
        float dist = sqrtf(dx * dx + dy * dy + dz * dz + 1e-6f);
        float ddz  = e2 / dist;
        float zdd  = (znx * dx + zny * dy + znz * dz) / dist;

        s_coords[k][0] = e0;  s_coords[k][1] = e1;  s_coords[k][2] = e2;
        s_coords[k][3] = idist; s_coords[k][4] = zz;
        s_coords[k][5] = ddz;   s_coords[k][6] = zdd; s_coords[k][7] = 0.0f;
    }
    __syncthreads();

    // gaussian: thread handles 4 k's with the SAME n (register-cached prec)
    {
        const int n  = tid & 31;
        const int k0 = tid >> 5;
        float ct[7], pr[49];
#pragma unroll
        for (int d = 0; d < 7; d++) ct[d] = s_cent[n][d];
#pragma unroll
        for (int i = 0; i < 49; i++) pr[i] = s_prec[n][i];
#pragma unroll
        for (int kk = 0; kk < 4; kk++) {
            const int k = k0 + kk * 4;
            float y0 = 0, y1 = 0, y2 = 0, y3 = 0, y4 = 0, y5 = 0, y6 = 0;
#pragma unroll
            for (int d = 0; d < 7; d++) {
                float diff = s_coords[k][d] - ct[d];
                y0 = fmaf(diff, pr[d * 7 + 0], y0);
                y1 = fmaf(diff, pr[d * 7 + 1], y1);
                y2 = fmaf(diff, pr[d * 7 + 2], y2);
                y3 = fmaf(diff, pr[d * 7 + 3], y3);
                y4 = fmaf(diff, pr[d * 7 + 4], y4);
                y5 = fmaf(diff, pr[d * 7 + 5], y5);
                y6 = fmaf(diff, pr[d * 7 + 6], y6);
            }
            float s = y0 * y0 + y1 * y1 + y2 * y2 + y3 * y3 + y4 * y4 + y5 * y5 + y6 * y6;
            s_emb[k][n] = __expf(-0.5f * s);
        }
    }
    __syncthreads();

    if (tid < 32) {
        float s = 0.0f;
#pragma unroll
        for (int k = 0; k < NK; k++) s += s_emb[k][tid];
        __nv_bfloat16 h = __float2bfloat16_rn(s);
        g_esum_hi[(size_t)bl * 32 + tid] = h;
        g_esum_lo[(size_t)bl * 32 + tid] = __float2bfloat16_rn(s - __bfloat162float(h));
    }

    // ---- outer: R10-exact (j = tid&63 column, iq row-quarter) ----
    const int j  = tid & 63;
    const int iq = tid >> 6;
    ull acc2[8];
#pragma unroll
    for (int r = 0; r < 8; r++) acc2[r] = 0ull;
#pragma unroll
    for (int k = 0; k < NK; k++) {
        float a = s_attr[k][j];
        ull ap = pack2(a, a);
        const ulonglong2* ep = (const ulonglong2*)&s_emb[k][iq * 16];
        ulonglong2 e0 = ep[0], e1 = ep[1];
        fma2(acc2[0], e0.x, ap); fma2(acc2[1], e0.y, ap);
        fma2(acc2[2], e1.x, ap); fma2(acc2[3], e1.y, ap);
        ulonglong2 e2 = ep[2], e3 = ep[3];
        fma2(acc2[4], e2.x, ap); fma2(acc2[5], e2.y, ap);
        fma2(acc2[6], e3.x, ap); fma2(acc2[7], e3.y, ap);
    }
    size_t base = (size_t)bl * 2048 + (size_t)iq * 1024 + j;
#pragma unroll
    for (int r = 0; r < 8; r++) {
        float2 f = unpack2(acc2[r]);
        size_t i0 = base + (size_t)(2 * r) * 64;
        size_t i1 = base + (size_t)(2 * r + 1) * 64;
        __nv_bfloat16 h0 = __float2bfloat16_rn(f.x);
        __nv_bfloat16 h1 = __float2bfloat16_rn(f.y);
        g_outer_hi[i0] = h0;
        g_outer_hi[i1] = h1;
        g_outer_lo[i0] = __float2bfloat16_rn(f.x - __bfloat162float(h0));
        g_outer_lo[i1] = __float2bfloat16_rn(f.y - __bfloat162float(h1));
    }
}

// ============================================================================
// Kernel C: HMMA GEMM, M=128 per CTA, 3-stage cp.async ring (215 KB smem).
// grid 128 CTAs x 256 threads (8 warps); warp tile 32x64; BK=64 (+K=32 tail).
// ============================================================================
#define LDA 72
#define LDB 136
#define ASZ (128 * LDA * 2)             // 18432 B per A buffer
#define BSZ (64 * LDB * 2)              // 17408 B per B buffer
#define BUFSZ (2 * ASZ + 2 * BSZ)       // 71680 B  [Ah][Al][Bh][Bl]
#define NSTAGE 3
#define GEMM_SMEM (NSTAGE * BUFSZ)      // 215040 B

__device__ __forceinline__ void ldm_x4(uint32_t& r0, uint32_t& r1,
                                       uint32_t& r2, uint32_t& r3, uint32_t a) {
    asm volatile("ldmatrix.sync.aligned.m8n8.x4.shared.b16 {%0,%1,%2,%3}, [%4];"
                 : "=r"(r0), "=r"(r1), "=r"(r2), "=r"(r3) : "r"(a));
}
__device__ __forceinline__ void ldm_x4t(uint32_t& r0, uint32_t& r1,
                                        uint32_t& r2, uint32_t& r3, uint32_t a) {
    asm volatile("ldmatrix.sync.aligned.m8n8.x4.trans.shared.b16 {%0,%1,%2,%3}, [%4];"
                 : "=r"(r0), "=r"(r1), "=r"(r2), "=r"(r3) : "r"(a));
}
__device__ __forceinline__ void mma_bf16(float* d, const uint32_t* a,
                                         uint32_t b0, uint32_t b1) {
    asm volatile(
        "mma.sync.aligned.m16n8k16.row.col.f32.bf16.bf16.f32 "
        "{%0,%1,%2,%3}, {%4,%5,%6,%7}, {%8,%9}, {%0,%1,%2,%3};"
        : "+f"(d[0]), "+f"(d[1]), "+f"(d[2]), "+f"(d[3])
        : "r"(a[0]), "r"(a[1]), "r"(a[2]), "r"(a[3]), "r"(b0), "r"(b1));
}

extern __shared__ uint8_t g_dsm[];

__global__ __launch_bounds__(256) void gemm_mma(
    const float* __restrict__ bias, float* __restrict__ out)
{
    const int tid    = threadIdx.x;
    const int wid    = tid >> 5;
    const int lane   = tid & 31;
    const int warp_m = wid & 3;          // 4 m-groups of 32 rows
    const int warp_n = wid >> 2;         // 2 n-groups of 64 cols
    const int rowBase = blockIdx.x * 128;

    const uint32_t smem0 = cvta_smem(g_dsm);

    const int r_a = tid >> 1;            // 0..127 (A row)
    const int h_a = (tid & 1) * 32;      // A col half (bf16)
    const int k_b = tid >> 2;            // 0..63  (B k-row)
    const int q_b = (tid & 3) * 32;      // B col quarter

    const int lrow = (lane & 7) + ((lane >> 3) & 1) * 8;
    const int lcol = (lane >> 4) * 8;
    const uint32_t aOffBase = (uint32_t)((warp_m * 32 + lrow) * LDA + lcol) * 2;
    const uint32_t bOffBase = (uint32_t)(lrow * LDB + warp_n * 64 + lcol) * 2;

    float acc[2][8][4];
#pragma unroll
    for (int mt = 0; mt < 2; mt++)
#pragma unroll
        for (int nt = 0; nt < 8; nt++)
#pragma unroll
            for (int r = 0; r < 4; r++) acc[mt][nt][r] = 0.0f;

    auto load_chunk = [&](int c, uint32_t sb) {
        const uint32_t sAh = sb, sAl = sb + ASZ, sBh = sb + 2 * ASZ, sBl = sb + 2 * ASZ + BSZ;
        if (c < 32) {
            const size_t aix = (size_t)(rowBase + r_a) * 2048 + c * 64 + h_a;
            const uint32_t aoff = (uint32_t)(r_a * LDA + h_a) * 2;
#pragma unroll
            for (int g = 0; g < 4; g++) {
                cpasync16(sAh + aoff + g * 16, &g_outer_hi[aix + g * 8]);
                cpasync16(sAl + aoff + g * 16, &g_outer_lo[aix + g * 8]);
            }
            const size_t bix = (size_t)(c * 64 + k_b) * 128 + q_b;
            const uint32_t boff = (uint32_t)(k_b * LDB + q_b) * 2;
#pragma unroll
            for (int g = 0; g < 4; g++) {
                cpasync16(sBh + boff + g * 16, &g_bt_hi[bix + g * 8]);
                cpasync16(sBl + boff + g * 16, &g_bt_lo[bix + g * 8]);
            }
        } else {
#pragma unroll
            for (int s = 0; s < 2; s++) {
                int idx = tid + s * 256;          // 0..511
                int row = idx >> 2;
                int ch  = idx & 3;                // 8-col chunk
                const size_t aix = (size_t)(rowBase + row) * 32 + ch * 8;
                const uint32_t aoff = (uint32_t)(row * LDA + ch * 8) * 2;
                cpasync16(sAh + aoff, &g_esum_hi[aix]);
                cpasync16(sAl + aoff, &g_esum_lo[aix]);
            }
#pragma unroll
            for (int s = 0; s < 2; s++) {
                int idx = tid + s * 256;          // 0..511
                int k   = idx >> 4;
                int ch  = idx & 15;               // 8-col chunk
                const size_t bix = (size_t)(2048 + k) * 128 + ch * 8;
                const uint32_t boff = (uint32_t)(k * LDB + ch * 8) * 2;
                cpasync16(sBh + boff, &g_bt_hi[bix]);
                cpasync16(sBl + boff, &g_bt_lo[bix]);
            }
        }
        asm volatile("cp.async.commit_group;" ::: "memory");
    };

    load_chunk(0, smem0);
    load_chunk(1, smem0 + BUFSZ);

    for (int c = 0; c <= 32; c++) {
        __syncthreads();                      // all warps done with buffer (c+2)%3
        if (c + 2 <= 32) load_chunk(c + 2, smem0 + ((c + 2) % NSTAGE) * BUFSZ);

        if (c <= 30)      asm volatile("cp.async.wait_group 2;" ::: "memory");
        else if (c == 31) asm volatile("cp.async.wait_group 1;" ::: "memory");
        else              asm volatile("cp.async.wait_group 0;" ::: "memory");
        __syncthreads();

        const uint32_t sb = smem0 + (c % NSTAGE) * BUFSZ;
        const uint32_t sAh = sb, sAl = sb + ASZ, sBh = sb + 2 * ASZ, sBl = sb + 2 * ASZ + BSZ;

        const int nks = (c == 32) ? 2 : 4;
        for (int ks = 0; ks < nks; ks++) {
            const uint32_t aAdd = (uint32_t)(ks * 16) * 2;
            const uint32_t bAdd = (uint32_t)(ks * 16 * LDB) * 2;
            uint32_t ah[2][4], al[2][4];
#pragma unroll
            for (int mt = 0; mt < 2; mt++) {
                uint32_t ao = aOffBase + (uint32_t)(mt * 16 * LDA) * 2 + aAdd;
                ldm_x4(ah[mt][0], ah[mt][1], ah[mt][2], ah[mt][3], sAh + ao);
                ldm_x4(al[mt][0], al[mt][1], al[mt][2], al[mt][3], sAl + ao);
            }
#pragma unroll
            for (int ng = 0; ng < 4; ng++) {
                uint32_t bo = bOffBase + (uint32_t)(ng * 16) * 2 + bAdd;
                uint32_t bh0, bh1, bh2, bh3, bl0, bl1, bl2, bl3;
                ldm_x4t(bh0, bh1, bh2, bh3, sBh + bo);
                ldm_x4t(bl0, bl1, bl2, bl3, sBl + bo);
#pragma unroll
                for (int mt = 0; mt < 2; mt++) {
                    mma_bf16(acc[mt][ng * 2],     ah[mt], bh0, bh1);
                    mma_bf16(acc[mt][ng * 2],     ah[mt], bl0, bl1);
                    mma_bf16(acc[mt][ng * 2],     al[mt], bh0, bh1);
                    mma_bf16(acc[mt][ng * 2 + 1], ah[mt], bh2, bh3);
                    mma_bf16(acc[mt][ng * 2 + 1], ah[mt], bl2, bl3);
                    mma_bf16(acc[mt][ng * 2 + 1], al[mt], bh2, bh3);
                }
            }
        }
    }

    const int gId = lane >> 2;
    const int tig = lane & 3;
#pragma unroll
    for (int mt = 0; mt < 2; mt++) {
#pragma unroll
        for (int nt = 0; nt < 8; nt++) {
            int col = warp_n * 64 + nt * 8 + tig * 2;
            float2 bv = *(const float2*)&bias[col];
            int m0 = rowBase + warp_m * 32 + mt * 16 + gId;
            float2 v0 = make_float2(acc[mt][nt][0] + bv.x, acc[mt][nt][1] + bv.y);
            float2 v1 = make_float2(acc[mt][nt][2] + bv.x, acc[mt][nt][3] + bv.y);
            *(float2*)&out[(size_t)m0 * 128 + col]       = v0;
            *(float2*)&out[(size_t)(m0 + 8) * 128 + col] = v1;
        }
    }
}

// ============================================================================
extern "C" void kernel_launch(void* const* d_in, const int* in_sizes, int n_in,
                              void* d_out, int out_size)
{
    const float* attr  = (const float*)d_in[0];
    const float* frame = (const float*)d_in[1];
    const int*   aidx  = (const int*)  d_in[2];
    // d_in[3] = labels (unused)
    const float* gkc   = (const float*)d_in[4];
    const float* gkp   = (const float*)d_in[5];
    const float* W12   = (const float*)d_in[6];
    const float* K1    = (const float*)d_in[7];
    const float* bias  = (const float*)d_in[8];
    float* out = (float*)d_out;

    static bool attr_set = false;
    if (!attr_set) {
        cudaFuncSetAttribute(gemm_mma, cudaFuncAttributeMaxDynamicSharedMemorySize,
                             GEMM_SMEM);
        attr_set = true;
    }

    pack_centers<<<64, 256>>>(frame);
    knn_kernel<<<2048, 256>>>();
    wsplit_kernel<<<1040, 256>>>(W12, K1);
    feat_kernel<<<NB * NL, 128>>>(attr, frame, aidx, gkc, gkp);
    gemm_mma<<<128, 256, GEMM_SMEM>>>(bias, out);
}

// round 16
// speedup vs baseline: 1.1881x; 1.0839x over previous
#include <cuda_runtime.h>
#include <cuda_bf16.h>
#include <cstdint>

#define NB   8
#define NL   2048
#define NK   16
#define NATT 64
#define NEMB 32
#define NOUT 128
#define KCAP 96

typedef unsigned long long ull;

// ---------------- scratch (device globals; no allocations allowed) ----------
__device__ int            g_nidx[NB * NL * NK];
__device__ float4         g_cent[NB * NL];
__device__ __nv_bfloat16  g_outer_hi[(size_t)NB * NL * 2048];   // 64 MB
__device__ __nv_bfloat16  g_outer_lo[(size_t)NB * NL * 2048];   // 64 MB
__device__ __nv_bfloat16  g_esum_hi[NB * NL * NEMB];
__device__ __nv_bfloat16  g_esum_lo[NB * NL * NEMB];
__device__ __nv_bfloat16  g_bt_hi[2080 * 128];                  // [W12;K1] [k][n]
__device__ __nv_bfloat16  g_bt_lo[2080 * 128];

// ---------------- helpers ---------------------------------------------------
__device__ __forceinline__ void fma2(ull& d, ull a, ull b) {
    asm("fma.rn.f32x2 %0, %1, %2, %3;" : "=l"(d) : "l"(a), "l"(b), "l"(d));
}
__device__ __forceinline__ ull pack2(float x, float y) {
    ull r; asm("mov.b64 %0, {%1, %2};" : "=l"(r) : "f"(x), "f"(y)); return r;
}
__device__ __forceinline__ float2 unpack2(ull v) {
    float2 f; asm("mov.b64 {%0, %1}, %2;" : "=f"(f.x), "=f"(f.y) : "l"(v)); return f;
}
__device__ __forceinline__ uint32_t cvta_smem(const void* p) {
    uint32_t a;
    asm("{ .reg .u64 t; cvta.to.shared.u64 t, %1; cvt.u32.u64 %0, t; }"
        : "=r"(a) : "l"(p));
    return a;
}
__device__ __forceinline__ void cpasync16(uint32_t dst, const void* src) {
    asm volatile("cp.async.cg.shared.global [%0], [%1], 16;"
                 :: "r"(dst), "l"(src) : "memory");
}
__device__ __forceinline__ ull umin64(ull a, ull b) { return a < b ? a : b; }

// ============================================================================
// Kernel A0: pack centers
// ============================================================================
__global__ __launch_bounds__(256) void pack_centers(const float* __restrict__ frame)
{
    int i = blockIdx.x * 256 + threadIdx.x;
    const float* p = frame + (size_t)i * 12;
    float x = p[0], y = p[1], z = p[2];
    float sq = fmaf(x, x, fmaf(y, y, z * z));
    g_cent[i] = make_float4(x, y, z, sq);
}

// ============================================================================
// Kernel W: split [W12;K1] -> bf16 hi/lo, layout [k][n] (k = 0..2079)
// ============================================================================
__global__ __launch_bounds__(256) void wsplit_kernel(
    const float* __restrict__ W12, const float* __restrict__ K1)
{
    int idx = blockIdx.x * 256 + threadIdx.x;
    float v;
    if (idx < 2048 * 128) v = W12[idx];
    else                  v = K1[idx - 2048 * 128];
    __nv_bfloat16 hi = __float2bfloat16_rn(v);
    __nv_bfloat16 lo = __float2bfloat16_rn(v - __bfloat162float(hi));
    g_bt_hi[idx] = hi;
    g_bt_lo[idx] = lo;
}

// ============================================================================
// Kernel A: KNN threshold-collect (unchanged from R13)
// ============================================================================
__global__ __launch_bounds__(256) void knn_kernel()
{
    __shared__ ull s_buf[8][KCAP];
    __shared__ ull s_merge[8][32 * 16];     // fallback only

    const int w    = threadIdx.x >> 5;
    const int lane = threadIdx.x & 31;
    const int q    = blockIdx.x * 8 + w;
    const int b    = q >> 11;

    const float4* __restrict__ cent = g_cent + b * NL;
    const float4 cq = cent[q & 2047];
    int* o = g_nidx + (size_t)q * NK;

    float m1 = __int_as_float(0x7F800000);
#pragma unroll 4
    for (int r = 0; r < 64; r++) {
        const int m = r * 32 + lane;
        float4 c = cent[m];
        float dot = fmaf(cq.x, c.x, fmaf(cq.y, c.y, cq.z * c.z));
        float d2  = fmaf(-2.0f, dot, cq.w + c.w);
        d2 = fmaxf(d2, 0.0f);
        m1 = fminf(m1, d2);
    }

    float v = m1;
#pragma unroll
    for (int k = 2; k <= 32; k <<= 1) {
#pragma unroll
        for (int j = k >> 1; j > 0; j >>= 1) {
            float ov = __shfl_xor_sync(0xFFFFFFFFu, v, j);
            bool up    = (lane & k) == 0;
            bool small = (lane & j) == 0;
            v = (small == up) ? fminf(v, ov) : fmaxf(v, ov);
        }
    }
    const float t = __shfl_sync(0xFFFFFFFFu, v, 15);

    int base = 0;
#pragma unroll 4
    for (int r = 0; r < 64; r++) {
        const int m = r * 32 + lane;
        float4 c = cent[m];
        float dot = fmaf(cq.x, c.x, fmaf(cq.y, c.y, cq.z * c.z));
        float d2  = fmaf(-2.0f, dot, cq.w + c.w);
        d2 = fmaxf(d2, 0.0f);
        bool keep = (d2 <= t);
        unsigned bal = __ballot_sync(0xFFFFFFFFu, keep);
        if (keep) {
            int pos = base + __popc(bal & ((1u << lane) - 1u));
            if (pos < KCAP)
                s_buf[w][pos] = ((ull)__float_as_uint(d2) << 32) | (unsigned)m;
        }
        base += __popc(bal);
    }
    __syncwarp();

    if (base <= KCAP) {
        for (int i = lane; i < KCAP; i += 32)
            if (i >= base) s_buf[w][i] = 0xFFFFFFFFFFFFFFFFull;
        __syncwarp();

        ull a0 = s_buf[w][lane];
        ull a1 = s_buf[w][lane + 32];
        ull a2 = s_buf[w][lane + 64];
#pragma unroll
        for (int r = 0; r < 16; r++) {
            ull mv = umin64(a0, umin64(a1, a2));
#pragma unroll
            for (int off = 16; off > 0; off >>= 1) {
                ull ov = __shfl_xor_sync(0xFFFFFFFFu, mv, off);
                mv = umin64(mv, ov);
            }
            if (a0 == mv)      a0 = 0xFFFFFFFFFFFFFFFFull;
            else if (a1 == mv) a1 = 0xFFFFFFFFFFFFFFFFull;
            else if (a2 == mv) a2 = 0xFFFFFFFFFFFFFFFFull;
            if (lane == 0) o[r] = (int)(unsigned)(mv & 0xFFFFFFFFull);
        }
    } else {
        float dl[16];
        int   il[16];
#pragma unroll
        for (int s = 0; s < 16; s++) { dl[s] = __int_as_float(0x7F800000); il[s] = -1; }
        for (int r = 0; r < 64; r++) {
            const int m = r * 32 + lane;
            float4 c = cent[m];
            float dot = fmaf(cq.x, c.x, fmaf(cq.y, c.y, cq.z * c.z));
            float d2  = fmaf(-2.0f, dot, cq.w + c.w);
            d2 = fmaxf(d2, 0.0f);
            if (d2 < dl[15]) {
                float cd = d2; int ci = m;
#pragma unroll
                for (int s = 0; s < 16; s++) {
                    bool  lt = cd < dl[s];
                    float td = dl[s]; int ti = il[s];
                    dl[s] = lt ? cd : td;  il[s] = lt ? ci : ti;
                    cd    = lt ? td : cd;  ci    = lt ? ti : ci;
                }
            }
        }
        ull* my = &s_merge[w][lane * 16];
#pragma unroll
        for (int s = 0; s < 16; s++)
            my[s] = ((ull)__float_as_uint(dl[s]) << 32) | (unsigned)il[s];
        __syncwarp();
        int p = 0;
        ull h = my[0];
        for (int r = 0; r < 16; r++) {
            ull mv = h;
#pragma unroll
            for (int off = 16; off > 0; off >>= 1) {
                ull ov = __shfl_xor_sync(0xFFFFFFFFu, mv, off);
                mv = umin64(mv, ov);
            }
            if (h == mv) {
                p++;
                h = (p < 16) ? my[p] : 0xFFFFFFFFFFFFFFFFull;
            }
            if (lane == 0) o[r] = (int)(unsigned)(mv & 0xFFFFFFFFull);
        }
    }
}

// ============================================================================
// Kernel B: feat — R13-exact (measured 115.7 us; regs=80, occ 35%)
// ============================================================================
__global__ __launch_bounds__(128) void feat_kernel(
    const float* __restrict__ attr,
    const float* __restrict__ frame,
    const int*   __restrict__ aidx,
    const float* __restrict__ gkc,
    const float* __restrict__ gkp)
{
    __shared__ int   s_nidx[NK];
    __shared__ float s_coords[NK][8];
    __shared__ float s_cent[32][9];
    __shared__ float s_prec[32][49];
    __shared__ float s_attr[NK][64];
    __shared__ float s_emb[NK][32];

    const int bl  = blockIdx.x;
    const int b   = bl >> 11;
    const int tid = threadIdx.x;

    if (tid < NK) s_nidx[tid] = g_nidx[(size_t)bl * NK + tid];
    for (int i = tid; i < 7 * 32; i += 128)
        s_cent[i & 31][i >> 5] = gkc[i];
    for (int i = tid; i < 49 * 32; i += 128)
        s_prec[i & 31][i >> 5] = gkp[i];
    __syncthreads();

    for (int i = tid; i < NK * 16; i += 128) {
        int k = i >> 4, j4 = i & 15;
        const float4* src = (const float4*)&attr[((size_t)(b * NL + s_nidx[k])) * 64];
        ((float4*)&s_attr[k][0])[j4] = src[j4];
    }

    if (tid < NK) {
        const int k = tid;
        const int m = s_nidx[k];
        const size_t gs = (size_t)bl * 12;
        const size_t gn = (size_t)(b * NL + m) * 12;

        float cx = frame[gs + 0], cy = frame[gs + 1], cz = frame[gs + 2];
        float r0x = frame[gs + 3], r0y = frame[gs + 4],  r0z = frame[gs + 5];
        float r1x = frame[gs + 6], r1y = frame[gs + 7],  r1z = frame[gs + 8];
        float r2x = frame[gs + 9], r2y = frame[gs + 10], r2z = frame[gs + 11];

        float dx = frame[gn + 0] - cx, dy = frame[gn + 1] - cy, dz = frame[gn + 2] - cz;
        float znx = frame[gn + 9], zny = frame[gn + 10], znz = frame[gn + 11];

        float e0 = dx * r0x + dy * r0y + dz * r0z;
        float e1 = dx * r1x + dy * r1y + dz * r1z;
        float e2 = dx * r2x + dy * r2y + dz * r2z;

        float idxs = (float)aidx[bl];
        float idxn = (float)aidx[b * NL + m];
        float idist = fminf(fabsf(idxn - idxs), 8.0f);

        float zz   = znx * r2x + zny * r2y + znz * r2z;
        float dist = sqrtf(dx * dx + dy * dy + dz * dz + 1e-6f);
        float ddz  = e2 / dist;
        float zdd  = (znx * dx + zny * dy + znz * dz) / dist;

        s_coords[k][0] = e0;  s_coords[k][1] = e1;  s_coords[k][2] = e2;
        s_coords[k][3] = idist; s_coords[k][4] = zz;
        s_coords[k][5] = ddz;   s_coords[k][6] = zdd; s_coords[k][7] = 0.0f;
    }
    __syncthreads();

    // gaussian: thread handles 4 k's with the SAME n (register-cached prec)
    {
        const int n  = tid & 31;
        const int k0 = tid >> 5;
        float ct[7], pr[49];
#pragma unroll
        for (int d = 0; d < 7; d++) ct[d] = s_cent[n][d];
#pragma unroll
        for (int i = 0; i < 49; i++) pr[i] = s_prec[n][i];
#pragma unroll
        for (int kk = 0; kk < 4; kk++) {
            const int k = k0 + kk * 4;
            float y0 = 0, y1 = 0, y2 = 0, y3 = 0, y4 = 0, y5 = 0, y6 = 0;
#pragma unroll
            for (int d = 0; d < 7; d++) {
                float diff = s_coords[k][d] - ct[d];
                y0 = fmaf(diff, pr[d * 7 + 0], y0);
                y1 = fmaf(diff, pr[d * 7 + 1], y1);
                y2 = fmaf(diff, pr[d * 7 + 2], y2);
                y3 = fmaf(diff, pr[d * 7 + 3], y3);
                y4 = fmaf(diff, pr[d * 7 + 4], y4);
                y5 = fmaf(diff, pr[d * 7 + 5], y5);
                y6 = fmaf(diff, pr[d * 7 + 6], y6);
            }
            float s = y0 * y0 + y1 * y1 + y2 * y2 + y3 * y3 + y4 * y4 + y5 * y5 + y6 * y6;
            s_emb[k][n] = __expf(-0.5f * s);
        }
    }
    __syncthreads();

    if (tid < 32) {
        float s = 0.0f;
#pragma unroll
        for (int k = 0; k < NK; k++) s += s_emb[k][tid];
        __nv_bfloat16 h = __float2bfloat16_rn(s);
        g_esum_hi[(size_t)bl * 32 + tid] = h;
        g_esum_lo[(size_t)bl * 32 + tid] = __float2bfloat16_rn(s - __bfloat162float(h));
    }

    // ---- outer: R10-exact (j = tid&63 column, iq row-quarter) ----
    const int j  = tid & 63;
    const int iq = tid >> 6;
    ull acc2[8];
#pragma unroll
    for (int r = 0; r < 8; r++) acc2[r] = 0ull;
#pragma unroll
    for (int k = 0; k < NK; k++) {
        float a = s_attr[k][j];
        ull ap = pack2(a, a);
        const ulonglong2* ep = (const ulonglong2*)&s_emb[k][iq * 16];
        ulonglong2 e0 = ep[0], e1 = ep[1];
        fma2(acc2[0], e0.x, ap); fma2(acc2[1], e0.y, ap);
        fma2(acc2[2], e1.x, ap); fma2(acc2[3], e1.y, ap);
        ulonglong2 e2 = ep[2], e3 = ep[3];
        fma2(acc2[4], e2.x, ap); fma2(acc2[5], e2.y, ap);
        fma2(acc2[6], e3.x, ap); fma2(acc2[7], e3.y, ap);
    }
    size_t base = (size_t)bl * 2048 + (size_t)iq * 1024 + j;
#pragma unroll
    for (int r = 0; r < 8; r++) {
        float2 f = unpack2(acc2[r]);
        size_t i0 = base + (size_t)(2 * r) * 64;
        size_t i1 = base + (size_t)(2 * r + 1) * 64;
        __nv_bfloat16 h0 = __float2bfloat16_rn(f.x);
        __nv_bfloat16 h1 = __float2bfloat16_rn(f.y);
        g_outer_hi[i0] = h0;
        g_outer_hi[i1] = h1;
        g_outer_lo[i0] = __float2bfloat16_rn(f.x - __bfloat162float(h0));
        g_outer_lo[i1] = __float2bfloat16_rn(f.y - __bfloat162float(h1));
    }
}

// ============================================================================
// Kernel C: HMMA GEMM, M=128 per CTA, 2-stage (R13 ring), 512 threads/16 warps.
// Warp tile 16x64 (8 m-groups x 2 n-groups) -> 4 warps/SMSP.
// ============================================================================
#define LDA 72
#define LDB 136
#define ASZ (128 * LDA * 2)             // 18432 B per A buffer
#define BSZ (64 * LDB * 2)              // 17408 B per B buffer
#define BUFSZ (2 * ASZ + 2 * BSZ)       // 71680 B  [Ah][Al][Bh][Bl]
#define GEMM_SMEM (2 * BUFSZ)           // 143360 B

__device__ __forceinline__ void ldm_x4(uint32_t& r0, uint32_t& r1,
                                       uint32_t& r2, uint32_t& r3, uint32_t a) {
    asm volatile("ldmatrix.sync.aligned.m8n8.x4.shared.b16 {%0,%1,%2,%3}, [%4];"
                 : "=r"(r0), "=r"(r1), "=r"(r2), "=r"(r3) : "r"(a));
}
__device__ __forceinline__ void ldm_x4t(uint32_t& r0, uint32_t& r1,
                                        uint32_t& r2, uint32_t& r3, uint32_t a) {
    asm volatile("ldmatrix.sync.aligned.m8n8.x4.trans.shared.b16 {%0,%1,%2,%3}, [%4];"
                 : "=r"(r0), "=r"(r1), "=r"(r2), "=r"(r3) : "r"(a));
}
__device__ __forceinline__ void mma_bf16(float* d, const uint32_t* a,
                                         uint32_t b0, uint32_t b1) {
    asm volatile(
        "mma.sync.aligned.m16n8k16.row.col.f32.bf16.bf16.f32 "
        "{%0,%1,%2,%3}, {%4,%5,%6,%7}, {%8,%9}, {%0,%1,%2,%3};"
        : "+f"(d[0]), "+f"(d[1]), "+f"(d[2]), "+f"(d[3])
        : "r"(a[0]), "r"(a[1]), "r"(a[2]), "r"(a[3]), "r"(b0), "r"(b1));
}

extern __shared__ uint8_t g_dsm[];

__global__ __launch_bounds__(512) void gemm_mma(
    const float* __restrict__ bias, float* __restrict__ out)
{
    const int tid    = threadIdx.x;
    const int wid    = tid >> 5;
    const int lane   = tid & 31;
    const int warp_m = wid & 7;          // 8 m-groups of 16 rows
    const int warp_n = wid >> 3;         // 2 n-groups of 64 cols
    const int rowBase = blockIdx.x * 128;

    const uint32_t smem0 = cvta_smem(g_dsm);

    // per-thread load coords (8 cp.async per chunk)
    const int r_a = tid >> 2;            // 0..127 (A row)
    const int c_a = (tid & 3) * 16;      // A col base (bf16), 2 x 16B
    const int k_b = tid >> 3;            // 0..63  (B k-row)
    const int q_b = (tid & 7) * 16;      // B col base (bf16), 2 x 16B

    const int lrow = (lane & 7) + ((lane >> 3) & 1) * 8;
    const int lcol = (lane >> 4) * 8;
    const uint32_t aOffBase = (uint32_t)((warp_m * 16 + lrow) * LDA + lcol) * 2;
    const uint32_t bOffBase = (uint32_t)(lrow * LDB + warp_n * 64 + lcol) * 2;

    float acc[8][4];
#pragma unroll
    for (int nt = 0; nt < 8; nt++)
#pragma unroll
        for (int r = 0; r < 4; r++) acc[nt][r] = 0.0f;

    auto load_chunk = [&](int c, uint32_t sb) {
        const uint32_t sAh = sb, sAl = sb + ASZ, sBh = sb + 2 * ASZ, sBl = sb + 2 * ASZ + BSZ;
        if (c < 32) {
            const size_t aix = (size_t)(rowBase + r_a) * 2048 + c * 64 + c_a;
            const uint32_t aoff = (uint32_t)(r_a * LDA + c_a) * 2;
#pragma unroll
            for (int g = 0; g < 2; g++) {
                cpasync16(sAh + aoff + g * 16, &g_outer_hi[aix + g * 8]);
                cpasync16(sAl + aoff + g * 16, &g_outer_lo[aix + g * 8]);
            }
            const size_t bix = (size_t)(c * 64 + k_b) * 128 + q_b;
            const uint32_t boff = (uint32_t)(k_b * LDB + q_b) * 2;
#pragma unroll
            for (int g = 0; g < 2; g++) {
                cpasync16(sBh + boff + g * 16, &g_bt_hi[bix + g * 8]);
                cpasync16(sBl + boff + g * 16, &g_bt_lo[bix + g * 8]);
            }
        } else {
            // tail: A = esum (128 x 32), B = K1 (32 x 128); 1 cp16 per array
            const int chA = (tid & 3) * 8;
            const size_t aix = (size_t)(rowBase + r_a) * 32 + chA;
            const uint32_t aoff = (uint32_t)(r_a * LDA + chA) * 2;
            cpasync16(sAh + aoff, &g_esum_hi[aix]);
            cpasync16(sAl + aoff, &g_esum_lo[aix]);
            const int kk = tid >> 4;          // 0..31
            const int chB = (tid & 15) * 8;
            const size_t bix = (size_t)(2048 + kk) * 128 + chB;
            const uint32_t boff = (uint32_t)(kk * LDB + chB) * 2;
            cpasync16(sBh + boff, &g_bt_hi[bix]);
            cpasync16(sBl + boff, &g_bt_lo[bix]);
        }
        asm volatile("cp.async.commit_group;" ::: "memory");
    };

    load_chunk(0, smem0);

    for (int c = 0; c <= 32; c++) {
        if (c < 32) load_chunk(c + 1, smem0 + ((c + 1) & 1) * BUFSZ);

        if (c < 32) asm volatile("cp.async.wait_group 1;" ::: "memory");
        else        asm volatile("cp.async.wait_group 0;" ::: "memory");
        __syncthreads();

        const uint32_t sb = smem0 + (c & 1) * BUFSZ;
        const uint32_t sAh = sb, sAl = sb + ASZ, sBh = sb + 2 * ASZ, sBl = sb + 2 * ASZ + BSZ;

        const int nks = (c == 32) ? 2 : 4;
        for (int ks = 0; ks < nks; ks++) {
            const uint32_t aAdd = (uint32_t)(ks * 16) * 2;
            const uint32_t bAdd = (uint32_t)(ks * 16 * LDB) * 2;
            uint32_t ah[4], al[4];
            {
                uint32_t ao = aOffBase + aAdd;
                ldm_x4(ah[0], ah[1], ah[2], ah[3], sAh + ao);
                ldm_x4(al[0], al[1], al[2], al[3], sAl + ao);
            }
#pragma unroll
            for (int ng = 0; ng < 4; ng++) {
                uint32_t bo = bOffBase + (uint32_t)(ng * 16) * 2 + bAdd;
                uint32_t bh0, bh1, bh2, bh3, bl0, bl1, bl2, bl3;
                ldm_x4t(bh0, bh1, bh2, bh3, sBh + bo);
                ldm_x4t(bl0, bl1, bl2, bl3, sBl + bo);
                mma_bf16(acc[ng * 2],     ah, bh0, bh1);
                mma_bf16(acc[ng * 2],     ah, bl0, bl1);
                mma_bf16(acc[ng * 2],     al, bh0, bh1);
                mma_bf16(acc[ng * 2 + 1], ah, bh2, bh3);
                mma_bf16(acc[ng * 2 + 1], ah, bl2, bl3);
                mma_bf16(acc[ng * 2 + 1], al, bh2, bh3);
            }
        }
        __syncthreads();
    }

    const int gId = lane >> 2;
    const int tig = lane & 3;
#pragma unroll
    for (int nt = 0; nt < 8; nt++) {
        int col = warp_n * 64 + nt * 8 + tig * 2;
        float2 bv = *(const float2*)&bias[col];
        int m0 = rowBase + warp_m * 16 + gId;
        float2 v0 = make_float2(acc[nt][0] + bv.x, acc[nt][1] + bv.y);
        float2 v1 = make_float2(acc[nt][2] + bv.x, acc[nt][3] + bv.y);
        *(float2*)&out[(size_t)m0 * 128 + col]       = v0;
        *(float2*)&out[(size_t)(m0 + 8) * 128 + col] = v1;
    }
}

// ============================================================================
extern "C" void kernel_launch(void* const* d_in, const int* in_sizes, int n_in,
                              void* d_out, int out_size)
{
    const float* attr  = (const float*)d_in[0];
    const float* frame = (const float*)d_in[1];
    const int*   aidx  = (const int*)  d_in[2];
    // d_in[3] = labels (unused)
    const float* gkc   = (const float*)d_in[4];
    const float* gkp   = (const float*)d_in[5];
    const float* W12   = (const float*)d_in[6];
    const float* K1    = (const float*)d_in[7];
    const float* bias  = (const float*)d_in[8];
    float* out = (float*)d_out;

    static bool attr_set = false;
    if (!attr_set) {
        cudaFuncSetAttribute(gemm_mma, cudaFuncAttributeMaxDynamicSharedMemorySize,
                             GEMM_SMEM);
        attr_set = true;
    }

    pack_centers<<<64, 256>>>(frame);
    knn_kernel<<<2048, 256>>>();
    wsplit_kernel<<<1040, 256>>>(W12, K1);
    feat_kernel<<<NB * NL, 128>>>(attr, frame, aidx, gkc, gkp);
    gemm_mma<<<128, 512, GEMM_SMEM>>>(bias, out);
}